// round 13
// baseline (speedup 1.0000x reference)
#include <cuda_runtime.h>
#include <cuda_bf16.h>
#include <cstdint>

#define N_NODESC 100000
#define N_EDGESC 1600000
#define NUM_GRAPHSC 1024
#define IN_FEATC 7
#define HC 128
#define H3C 384
#define BN_EPSF 1e-5f

// ---------------- scratch (static device globals; no runtime alloc) ----------------
__device__ float g_z0[(size_t)N_NODESC * IN_FEATC];
__device__ float g_z[(size_t)N_NODESC * HC];
__device__ float g_hcat[(size_t)N_NODESC * H3C];
__device__ float g_pool[(size_t)NUM_GRAPHSC * H3C];
__device__ float g_z1[(size_t)NUM_GRAPHSC * 256];
__device__ int   g_deg[N_NODESC];
__device__ int   g_ptr[N_NODESC + 1];
__device__ int   g_cur[N_NODESC];
__device__ int   g_col[N_EDGESC];
__device__ int   g_gstart[NUM_GRAPHSC + 1];

// pre-split transposed weights, stored as the exact smem plane image:
// plane = 128 rows (n) x 68 u32 words (64 data = 128 bf16 k-values + 4 pad)
#define PLANE_W 68
#define PLANE_U32 (128 * PLANE_W)
__device__ uint32_t g_wbhi[5 * PLANE_U32];
__device__ uint32_t g_wblo[5 * PLANE_U32];

// ---------------- helpers ----------------
__device__ __forceinline__ uint32_t smem_u32(const void* p) {
    uint32_t a;
    asm("{ .reg .u64 t; cvta.to.shared.u64 t, %1; cvt.u32.u64 %0, t; }" : "=r"(a) : "l"(p));
    return a;
}
__device__ __forceinline__ void split2(float v0, float v1, uint32_t& hi, uint32_t& lo) {
    __nv_bfloat16 h0 = __float2bfloat16(v0);
    __nv_bfloat16 h1 = __float2bfloat16(v1);
    float r0 = v0 - __bfloat162float(h0);
    float r1 = v1 - __bfloat162float(h1);
    __nv_bfloat16 l0 = __float2bfloat16(r0);
    __nv_bfloat16 l1 = __float2bfloat16(r1);
    hi = (uint32_t)__bfloat16_as_ushort(h0) | ((uint32_t)__bfloat16_as_ushort(h1) << 16);
    lo = (uint32_t)__bfloat16_as_ushort(l0) | ((uint32_t)__bfloat16_as_ushort(l1) << 16);
}
__device__ __forceinline__ void ldsm4(uint32_t& r0, uint32_t& r1, uint32_t& r2, uint32_t& r3,
                                      uint32_t addr) {
    asm volatile("ldmatrix.sync.aligned.m8n8.x4.shared.b16 {%0,%1,%2,%3}, [%4];"
                 : "=r"(r0), "=r"(r1), "=r"(r2), "=r"(r3) : "r"(addr));
}
__device__ __forceinline__ void mma_bf16(float* c, const uint32_t* a, uint32_t b0, uint32_t b1) {
    asm volatile(
        "mma.sync.aligned.m16n8k16.row.col.f32.bf16.bf16.f32 "
        "{%0,%1,%2,%3}, {%4,%5,%6,%7}, {%8,%9}, {%0,%1,%2,%3};"
        : "+f"(c[0]), "+f"(c[1]), "+f"(c[2]), "+f"(c[3])
        : "r"(a[0]), "r"(a[1]), "r"(a[2]), "r"(a[3]), "r"(b0), "r"(b1));
}
__device__ __forceinline__ void cp16(uint32_t dst, const void* src) {
    asm volatile("cp.async.cg.shared.global [%0], [%1], 16;" :: "r"(dst), "l"(src));
}

// ---------------- CSR build ----------------
__global__ void k_zero_deg() {
    int i = blockIdx.x * blockDim.x + threadIdx.x;
    if (i < N_NODESC) g_deg[i] = 0;
}

__global__ void k_hist(const int* __restrict__ ei) {
    int stride = gridDim.x * blockDim.x;
    for (int e = blockIdx.x * blockDim.x + threadIdx.x; e < N_EDGESC; e += stride)
        atomicAdd(&g_deg[ei[N_EDGESC + e]], 1);
}

__global__ void k_scan(const int* __restrict__ batch) {
    __shared__ int s[1024];
    const int t = threadIdx.x;
    const int CHUNK = 98;
    int base = t * CHUNK;
    int loc = 0;
    for (int i = 0; i < CHUNK; ++i) {
        int idx = base + i;
        if (idx < N_NODESC) loc += g_deg[idx];
    }
    s[t] = loc;
    __syncthreads();
    for (int off = 1; off < 1024; off <<= 1) {
        int v = (t >= off) ? s[t - off] : 0;
        __syncthreads();
        s[t] += v;
        __syncthreads();
    }
    int run = s[t] - loc;
    for (int i = 0; i < CHUNK; ++i) {
        int idx = base + i;
        if (idx < N_NODESC) {
            g_ptr[idx] = run;
            g_cur[idx] = run;
            run += g_deg[idx];
        }
    }
    if (t == 1023) g_ptr[N_NODESC] = s[1023];
    {
        int g = t;
        int lo = 0, hi = N_NODESC;
        while (lo < hi) {
            int mid = (lo + hi) >> 1;
            if (batch[mid] < g) lo = mid + 1; else hi = mid;
        }
        g_gstart[g] = lo;
        if (t == 1023) g_gstart[NUM_GRAPHSC] = N_NODESC;
    }
}

__global__ void k_scatter(const int* __restrict__ ei) {
    int stride = gridDim.x * blockDim.x;
    for (int e = blockIdx.x * blockDim.x + threadIdx.x; e < N_EDGESC; e += stride) {
        int d = ei[N_EDGESC + e];
        int p = atomicAdd(&g_cur[d], 1);
        g_col[p] = ei[e];
    }
}

// ---------------- weight prep: W[k][n] -> BT planes [n][k] bf16 hi/lo ----------------
__global__ void k_wprep(const float* __restrict__ w0, const float* __restrict__ w1,
                        const float* __restrict__ w2, const float* __restrict__ w3,
                        const float* __restrict__ w4) {
    int widx = blockIdx.x;
    const float* w = (widx == 0) ? w0 : (widx == 1) ? w1 : (widx == 2) ? w2
                     : (widx == 3) ? w3 : w4;
    for (int it = 0; it < 32; ++it) {
        int lin = threadIdx.x + it * 256;     // 0..8191
        int kp = lin & 63;
        int n = lin >> 6;
        float v0 = w[(2 * kp) * 128 + n];
        float v1 = w[(2 * kp + 1) * 128 + n];
        uint32_t hi, lo;
        split2(v0, v1, hi, lo);
        int idx = widx * PLANE_U32 + n * PLANE_W + kp;
        g_wbhi[idx] = hi;
        g_wblo[idx] = lo;
    }
    if (threadIdx.x < 128) {
        int n = threadIdx.x;
#pragma unroll
        for (int p = 64; p < 68; ++p) {
            g_wbhi[widx * PLANE_U32 + n * PLANE_W + p] = 0;
            g_wblo[widx * PLANE_U32 + n * PLANE_W + p] = 0;
        }
    }
}

// ---------------- layer 0 aggregation (7 feats) ----------------
__global__ void k_agg0(const float* __restrict__ x) {
    int gidx = blockIdx.x * blockDim.x + threadIdx.x;
    int node = gidx >> 5;
    int lane = gidx & 31;
    if (node >= N_NODESC) return;
    float acc[IN_FEATC];
#pragma unroll
    for (int f = 0; f < IN_FEATC; ++f) acc[f] = 0.f;
    int s = g_ptr[node], e = g_ptr[node + 1];
    for (int p = s + lane; p < e; p += 32) {
        int src = g_col[p];
        const float* xp = x + (size_t)src * IN_FEATC;
#pragma unroll
        for (int f = 0; f < IN_FEATC; ++f) acc[f] += xp[f];
    }
#pragma unroll
    for (int f = 0; f < IN_FEATC; ++f) {
#pragma unroll
        for (int off = 16; off > 0; off >>= 1)
            acc[f] += __shfl_down_sync(0xffffffffu, acc[f], off);
    }
    if (lane == 0) {
        const float* xp = x + (size_t)node * IN_FEATC;
        float* zp = g_z0 + (size_t)node * IN_FEATC;
#pragma unroll
        for (int f = 0; f < IN_FEATC; ++f) zp[f] = xp[f] + acc[f];
    }
}

// ---------------- main aggregation: z[n] = h[n] + sum h[src] (8x unrolled gather) ----------------
__global__ void k_agg(const float* __restrict__ h, int ldh) {
    int gidx = blockIdx.x * blockDim.x + threadIdx.x;
    int node = gidx >> 5;
    int lane = gidx & 31;
    if (node >= N_NODESC) return;
    int fo = lane << 2;
    const float* hp = h + fo;
    float4 acc = *(const float4*)(h + (size_t)node * ldh + fo);
    int s = g_ptr[node], e = g_ptr[node + 1];
    int p = s;
    for (; p + 8 <= e; p += 8) {
        int i0 = g_col[p],     i1 = g_col[p + 1];
        int i2 = g_col[p + 2], i3 = g_col[p + 3];
        int i4 = g_col[p + 4], i5 = g_col[p + 5];
        int i6 = g_col[p + 6], i7 = g_col[p + 7];
        float4 v0 = *(const float4*)(hp + (size_t)i0 * ldh);
        float4 v1 = *(const float4*)(hp + (size_t)i1 * ldh);
        float4 v2 = *(const float4*)(hp + (size_t)i2 * ldh);
        float4 v3 = *(const float4*)(hp + (size_t)i3 * ldh);
        float4 v4 = *(const float4*)(hp + (size_t)i4 * ldh);
        float4 v5 = *(const float4*)(hp + (size_t)i5 * ldh);
        float4 v6 = *(const float4*)(hp + (size_t)i6 * ldh);
        float4 v7 = *(const float4*)(hp + (size_t)i7 * ldh);
        acc.x += ((v0.x + v1.x) + (v2.x + v3.x)) + ((v4.x + v5.x) + (v6.x + v7.x));
        acc.y += ((v0.y + v1.y) + (v2.y + v3.y)) + ((v4.y + v5.y) + (v6.y + v7.y));
        acc.z += ((v0.z + v1.z) + (v2.z + v3.z)) + ((v4.z + v5.z) + (v6.z + v7.z));
        acc.w += ((v0.w + v1.w) + (v2.w + v3.w)) + ((v4.w + v5.w) + (v6.w + v7.w));
    }
    for (; p < e; ++p) {
        int src = g_col[p];
        float4 v = *(const float4*)(hp + (size_t)src * ldh);
        acc.x += v.x; acc.y += v.y; acc.z += v.z; acc.w += v.w;
    }
    *(float4*)(g_z + (size_t)node * HC + fo) = acc;
}

// ---------------- tensor-core MLP via mma.sync bf16 3-term split ----------------
// smem byte layout: biases + A hi/lo + B1 hi/lo + B2 hi/lo (all planes resident)
#define ROW_B 272                 // bytes per plane row (68 u32)
#define PLANE_B (128 * ROW_B)     // 34816
#define SM_BS1 0
#define SM_BS2 512
#define SM_AHI 1024
#define SM_ALO (1024 + PLANE_B)
#define SM_B1H (1024 + 2 * PLANE_B)
#define SM_B1L (1024 + 3 * PLANE_B)
#define SM_B2H (1024 + 4 * PLANE_B)
#define SM_B2L (1024 + 5 * PLANE_B)
#define SM_TOTAL (1024 + 6 * PLANE_B)   // 209920 bytes

// per-warp mainloop: acc[2][8][4] over 32 rows (m0) x 64 cols (n0)
__device__ __forceinline__ void mma_main(uint32_t ahi, uint32_t alo, uint32_t bhi, uint32_t blo,
                                         int m0, int n0, int lane, float acc[2][8][4]) {
#pragma unroll
    for (int i = 0; i < 2; ++i)
#pragma unroll
        for (int j = 0; j < 8; ++j)
#pragma unroll
            for (int q = 0; q < 4; ++q) acc[i][j][q] = 0.f;

    const uint32_t a_off = (uint32_t)(m0 + (lane & 15)) * ROW_B + ((lane & 16) ? 16 : 0);
    const uint32_t b_off = (uint32_t)(n0 + (lane & 7) + ((lane & 16) ? 8 : 0)) * ROW_B
                           + ((lane & 8) ? 16 : 0);
#pragma unroll
    for (int ks = 0; ks < 8; ++ks) {
        const uint32_t kb = ks * 32;
        uint32_t Ah[2][4], Al[2][4];
#pragma unroll
        for (int mt = 0; mt < 2; ++mt) {
            uint32_t ad = a_off + (uint32_t)(mt * 16) * ROW_B + kb;
            ldsm4(Ah[mt][0], Ah[mt][1], Ah[mt][2], Ah[mt][3], ahi + ad);
            ldsm4(Al[mt][0], Al[mt][1], Al[mt][2], Al[mt][3], alo + ad);
        }
#pragma unroll
        for (int np = 0; np < 4; ++np) {
            uint32_t bd = b_off + (uint32_t)(np * 16) * ROW_B + kb;
            uint32_t Bh[4], Bl[4];
            ldsm4(Bh[0], Bh[1], Bh[2], Bh[3], bhi + bd);
            ldsm4(Bl[0], Bl[1], Bl[2], Bl[3], blo + bd);
#pragma unroll
            for (int sub = 0; sub < 2; ++sub) {
                int nt = np * 2 + sub;
#pragma unroll
                for (int mt = 0; mt < 2; ++mt) {
                    float* c = acc[mt][nt];
                    mma_bf16(c, Ah[mt], Bh[sub * 2], Bh[sub * 2 + 1]);
                    mma_bf16(c, Ah[mt], Bl[sub * 2], Bl[sub * 2 + 1]);
                    mma_bf16(c, Al[mt], Bh[sub * 2], Bh[sub * 2 + 1]);
                }
            }
        }
    }
}

// mode 0: A = relu(z0 @ wraw + bias1) computed in-kernel (K=7), then GEMM(B1)+bias2 -> OUT
// mode 1: A = split(Ain), GEMM(B1)+bias1 -> relu -> split -> GEMM(B2)+bias2 -> OUT
__global__ void __launch_bounds__(256, 1)
k_mlp(const float* __restrict__ Ain, int mode, const float* __restrict__ wraw,
      const float* __restrict__ bias1, int bidx1, int bidx2,
      const float* __restrict__ bias2,
      float* __restrict__ OUT, int ldout, int M) {
    extern __shared__ char sm[];
    const uint32_t smb = smem_u32(sm);
    float* bs1 = (float*)(sm + SM_BS1);
    float* bs2 = (float*)(sm + SM_BS2);
    const int tid = threadIdx.x;
    const int lane = tid & 31;
    const int warp = tid >> 5;
    const int g = lane >> 2, tg = lane & 3;
    const int row0 = blockIdx.x * 128;
    const int m0 = (warp & 3) * 32;
    const int n0 = (warp >> 2) * 64;

    // async-stage weight planes (B1; and B2 for mode 1)
    {
        const uint4* s1h = (const uint4*)(g_wbhi + bidx1 * PLANE_U32);
        const uint4* s1l = (const uint4*)(g_wblo + bidx1 * PLANE_U32);
        const uint4* s2h = (const uint4*)(g_wbhi + bidx2 * PLANE_U32);
        const uint4* s2l = (const uint4*)(g_wblo + bidx2 * PLANE_U32);
        for (int i = tid; i < PLANE_U32 / 4; i += 256) {
            cp16(smb + SM_B1H + i * 16, s1h + i);
            cp16(smb + SM_B1L + i * 16, s1l + i);
            if (mode) {
                cp16(smb + SM_B2H + i * 16, s2h + i);
                cp16(smb + SM_B2L + i * 16, s2l + i);
            }
        }
        asm volatile("cp.async.commit_group;" ::: "memory");
        if (tid < 128) {
            bs1[tid] = bias1[tid];
            bs2[tid] = bias2[tid];
        }
    }

    if (mode == 0) {
        // fused fc7: stage z0 tile + w1 raw into (unused) B2 region
        float* z0s = (float*)(sm + SM_B2H);            // 128*7 floats
        float* ws  = (float*)(sm + SM_B2L);            // 7*128 floats
        for (int i = tid; i < 128 * IN_FEATC; i += 256) {
            int r = i / IN_FEATC, k = i % IN_FEATC;
            int row = row0 + r;
            z0s[i] = (row < M) ? Ain[(size_t)row * IN_FEATC + k] : 0.f;
        }
        for (int i = tid; i < IN_FEATC * HC; i += 256) ws[i] = wraw[i];
        __syncthreads();
#pragma unroll 4
        for (int it = 0; it < 16; ++it) {
            int lin = tid + it * 256;
            int r = lin >> 5;
            int k4 = (lin & 31) << 2;
            float o[4];
#pragma unroll
            for (int j = 0; j < 4; ++j) {
                int c = k4 + j;
                float a = bs1[c];
#pragma unroll
                for (int kk = 0; kk < IN_FEATC; ++kk)
                    a = fmaf(z0s[r * IN_FEATC + kk], ws[kk * HC + c], a);
                o[j] = fmaxf(a, 0.f);
            }
            uint32_t h0, l0, h1, l1;
            split2(o[0], o[1], h0, l0);
            split2(o[2], o[3], h1, l1);
            uint32_t off = (uint32_t)r * ROW_B + (uint32_t)k4 * 2;
            *(uint2*)(sm + SM_AHI + off) = make_uint2(h0, h1);
            *(uint2*)(sm + SM_ALO + off) = make_uint2(l0, l1);
        }
    } else {
        // stage A: fp32 gmem (stride HC) -> split bf16 hi/lo planes
#pragma unroll 4
        for (int it = 0; it < 16; ++it) {
            int lin = tid + it * 256;
            int r = lin >> 5;
            int k4 = (lin & 31) << 2;
            float4 v = make_float4(0.f, 0.f, 0.f, 0.f);
            int row = row0 + r;
            if (row < M) v = *(const float4*)(Ain + (size_t)row * HC + k4);
            uint32_t h0, l0, h1, l1;
            split2(v.x, v.y, h0, l0);
            split2(v.z, v.w, h1, l1);
            uint32_t off = (uint32_t)r * ROW_B + (uint32_t)k4 * 2;
            *(uint2*)(sm + SM_AHI + off) = make_uint2(h0, h1);
            *(uint2*)(sm + SM_ALO + off) = make_uint2(l0, l1);
        }
    }
    asm volatile("cp.async.wait_group 0;" ::: "memory");
    __syncthreads();

    float acc[2][8][4];
    mma_main(smb + SM_AHI, smb + SM_ALO, smb + SM_B1H, smb + SM_B1L, m0, n0, lane, acc);

    if (mode == 0) {
        // epilogue: OUT = relu(acc + bias2)
#pragma unroll
        for (int mt = 0; mt < 2; ++mt) {
#pragma unroll
            for (int nt = 0; nt < 8; ++nt) {
                int c = n0 + nt * 8 + 2 * tg;
                float bx = bs2[c], by = bs2[c + 1];
                int ra = row0 + m0 + mt * 16 + g;
                int rb = ra + 8;
                if (ra < M) {
                    float2 v = make_float2(fmaxf(acc[mt][nt][0] + bx, 0.f),
                                           fmaxf(acc[mt][nt][1] + by, 0.f));
                    *(float2*)(OUT + (size_t)ra * ldout + c) = v;
                }
                if (rb < M) {
                    float2 v = make_float2(fmaxf(acc[mt][nt][2] + bx, 0.f),
                                           fmaxf(acc[mt][nt][3] + by, 0.f));
                    *(float2*)(OUT + (size_t)rb * ldout + c) = v;
                }
            }
        }
        return;
    }

    __syncthreads();  // all warps done reading A planes

    // t = relu(acc + bias1) -> split back into A planes
#pragma unroll
    for (int mt = 0; mt < 2; ++mt) {
#pragma unroll
        for (int nt = 0; nt < 8; ++nt) {
            int c = n0 + nt * 8 + 2 * tg;
            float bx = bs1[c], by = bs1[c + 1];
            int ra = m0 + mt * 16 + g;
            int rb = ra + 8;
            uint32_t hi, lo;
            split2(fmaxf(acc[mt][nt][0] + bx, 0.f), fmaxf(acc[mt][nt][1] + by, 0.f), hi, lo);
            uint32_t off = (uint32_t)ra * ROW_B + (uint32_t)c * 2;
            *(uint32_t*)(sm + SM_AHI + off) = hi;
            *(uint32_t*)(sm + SM_ALO + off) = lo;
            split2(fmaxf(acc[mt][nt][2] + bx, 0.f), fmaxf(acc[mt][nt][3] + by, 0.f), hi, lo);
            off = (uint32_t)rb * ROW_B + (uint32_t)c * 2;
            *(uint32_t*)(sm + SM_AHI + off) = hi;
            *(uint32_t*)(sm + SM_ALO + off) = lo;
        }
    }
    __syncthreads();

    mma_main(smb + SM_AHI, smb + SM_ALO, smb + SM_B2H, smb + SM_B2L, m0, n0, lane, acc);

    // final epilogue: OUT = relu(acc + bias2)
#pragma unroll
    for (int mt = 0; mt < 2; ++mt) {
#pragma unroll
        for (int nt = 0; nt < 8; ++nt) {
            int c = n0 + nt * 8 + 2 * tg;
            float bx = bs2[c], by = bs2[c + 1];
            int ra = row0 + m0 + mt * 16 + g;
            int rb = ra + 8;
            if (ra < M) {
                float2 v = make_float2(fmaxf(acc[mt][nt][0] + bx, 0.f),
                                       fmaxf(acc[mt][nt][1] + by, 0.f));
                *(float2*)(OUT + (size_t)ra * ldout + c) = v;
            }
            if (rb < M) {
                float2 v = make_float2(fmaxf(acc[mt][nt][2] + bx, 0.f),
                                       fmaxf(acc[mt][nt][3] + by, 0.f));
                *(float2*)(OUT + (size_t)rb * ldout + c) = v;
            }
        }
    }
}

// ---------------- global add pool ----------------
__global__ void k_pool() {
    int g = blockIdx.x;
    int f = threadIdx.x;
    int s = g_gstart[g], e = g_gstart[g + 1];
    float acc = 0.f;
    for (int n = s; n < e; ++n) acc += g_hcat[(size_t)n * H3C + f];
    g_pool[(size_t)g * H3C + f] = acc;
}

// ---------------- classifier stage 1 ----------------
__global__ void k_clf1(const float* __restrict__ w, const float* __restrict__ b,
                       const float* __restrict__ gamma, const float* __restrict__ beta,
                       const float* __restrict__ mean, const float* __restrict__ var) {
    __shared__ float gs[16 * H3C];
    const int r0 = blockIdx.x * 16;
    for (int i = threadIdx.x; i < 16 * H3C; i += blockDim.x)
        gs[i] = g_pool[(size_t)r0 * H3C + i];
    __syncthreads();
    const int c = threadIdx.x;
    float acc[16];
#pragma unroll
    for (int i = 0; i < 16; ++i) acc[i] = 0.f;
    for (int k = 0; k < H3C; ++k) {
        float wv = w[k * 256 + c];
#pragma unroll
        for (int i = 0; i < 16; ++i) acc[i] = fmaf(gs[i * H3C + k], wv, acc[i]);
    }
    float bb = b[c];
    float sc = rsqrtf(var[c] + BN_EPSF) * gamma[c];
    float mn = mean[c];
    float bt = beta[c];
#pragma unroll
    for (int i = 0; i < 16; ++i) {
        float v = (acc[i] + bb - mn) * sc + bt;
        g_z1[(size_t)(r0 + i) * 256 + c] = fmaxf(v, 0.f);
    }
}

// ---------------- classifier stage 2 ----------------
__global__ void k_clf2(const float* __restrict__ w2, const float* __restrict__ b2,
                       float* __restrict__ out) {
    __shared__ float w2s[512];
    __shared__ float b2s[2];
    for (int i = threadIdx.x; i < 512; i += blockDim.x) w2s[i] = w2[i];
    if (threadIdx.x < 2) b2s[threadIdx.x] = b2[threadIdx.x];
    __syncthreads();
    int warp = threadIdx.x >> 5;
    int lane = threadIdx.x & 31;
    int r = blockIdx.x * 8 + warp;
    float a0 = 0.f, a1 = 0.f;
    for (int k = lane; k < 256; k += 32) {
        float v = g_z1[(size_t)r * 256 + k];
        a0 = fmaf(v, w2s[2 * k], a0);
        a1 = fmaf(v, w2s[2 * k + 1], a1);
    }
#pragma unroll
    for (int off = 16; off > 0; off >>= 1) {
        a0 += __shfl_down_sync(0xffffffffu, a0, off);
        a1 += __shfl_down_sync(0xffffffffu, a1, off);
    }
    if (lane == 0) {
        out[2 * r] = a0 + b2s[0];
        out[2 * r + 1] = a1 + b2s[1];
    }
}

// ---------------- launch ----------------
extern "C" void kernel_launch(void* const* d_in, const int* in_sizes, int n_in,
                              void* d_out, int out_size) {
    const float* x      = (const float*)d_in[0];
    const int*   ei     = (const int*)d_in[1];
    const int*   batch  = (const int*)d_in[2];
    const float* w1[3]  = {(const float*)d_in[3], (const float*)d_in[7],  (const float*)d_in[11]};
    const float* b1[3]  = {(const float*)d_in[4], (const float*)d_in[8],  (const float*)d_in[12]};
    const float* w2[3]  = {(const float*)d_in[5], (const float*)d_in[9],  (const float*)d_in[13]};
    const float* b2[3]  = {(const float*)d_in[6], (const float*)d_in[10], (const float*)d_in[14]};
    const float* clf_w1 = (const float*)d_in[15];
    const float* clf_b1 = (const float*)d_in[16];
    const float* clf_w2 = (const float*)d_in[17];
    const float* clf_b2 = (const float*)d_in[18];
    const float* bn_g   = (const float*)d_in[19];
    const float* bn_b   = (const float*)d_in[20];
    const float* bn_m   = (const float*)d_in[21];
    const float* bn_v   = (const float*)d_in[22];
    float* out = (float*)d_out;

    float *p_z0, *p_z, *p_hcat;
    cudaGetSymbolAddress((void**)&p_z0, g_z0);
    cudaGetSymbolAddress((void**)&p_z, g_z);
    cudaGetSymbolAddress((void**)&p_hcat, g_hcat);

    cudaFuncSetAttribute(k_mlp, cudaFuncAttributeMaxDynamicSharedMemorySize, SM_TOTAL);

    // CSR build + weight prep
    k_zero_deg<<<(N_NODESC + 255) / 256, 256>>>();
    k_hist<<<1024, 256>>>(ei);
    k_scan<<<1, 1024>>>(batch);
    k_scatter<<<1024, 256>>>(ei);
    // weight plane order: 0=w2_0, 1=w1_1, 2=w2_1, 3=w1_2, 4=w2_2
    k_wprep<<<5, 256>>>(w2[0], w1[1], w2[1], w1[2], w2[2]);

    const int aggBlocks = N_NODESC / 8;
    const int gemmBlocks = (N_NODESC + 127) / 128;

    // layer 0: agg(7) -> fused fc7 + tensor GEMM
    k_agg0<<<aggBlocks, 256>>>(x);
    k_mlp<<<gemmBlocks, 256, SM_TOTAL>>>(p_z0, 0, w1[0], b1[0], 0, 0, b2[0],
                                         p_hcat + 0, H3C, N_NODESC);

    // layers 1,2: agg -> fused two-stage tensor MLP
    for (int l = 1; l < 3; ++l) {
        k_agg<<<aggBlocks, 256>>>(p_hcat + (l - 1) * HC, H3C);
        int wa = (l == 1) ? 1 : 3;
        int wb = (l == 1) ? 2 : 4;
        k_mlp<<<gemmBlocks, 256, SM_TOTAL>>>(p_z, 1, w1[l], b1[l], wa, wb, b2[l],
                                             p_hcat + l * HC, H3C, N_NODESC);
    }

    // pool + classifier
    k_pool<<<NUM_GRAPHSC, H3C>>>();
    k_clf1<<<NUM_GRAPHSC / 16, 256>>>(clf_w1, clf_b1, bn_g, bn_b, bn_m, bn_v);
    k_clf2<<<NUM_GRAPHSC / 8, 256>>>(clf_w2, clf_b2, out);
}

// round 15
// speedup vs baseline: 1.6019x; 1.6019x over previous
#include <cuda_runtime.h>
#include <cuda_bf16.h>
#include <cstdint>

#define N_NODESC 100000
#define N_EDGESC 1600000
#define NUM_GRAPHSC 1024
#define IN_FEATC 7
#define HC 128
#define H3C 384
#define BN_EPSF 1e-5f

// ---------------- scratch (static device globals; no runtime alloc) ----------------
__device__ float g_z0[(size_t)N_NODESC * IN_FEATC];
__device__ float g_z[(size_t)N_NODESC * HC];
__device__ float g_hcat[(size_t)N_NODESC * H3C];
__device__ float g_pool[(size_t)NUM_GRAPHSC * H3C];
__device__ float g_z1[(size_t)NUM_GRAPHSC * 256];
__device__ int   g_deg[N_NODESC];
__device__ int   g_ptr[N_NODESC + 1];
__device__ int   g_cur[N_NODESC];
__device__ int   g_col[N_EDGESC];
__device__ int   g_gstart[NUM_GRAPHSC + 1];

// pre-split transposed weights, stored as the exact smem plane image:
// plane = 128 rows (n) x 68 u32 words (64 data = 128 bf16 k-values + 4 pad)
#define PLANE_W 68
#define PLANE_U32 (128 * PLANE_W)
__device__ uint32_t g_wbhi[5 * PLANE_U32];
__device__ uint32_t g_wblo[5 * PLANE_U32];

// ---------------- helpers ----------------
__device__ __forceinline__ uint32_t smem_u32(const void* p) {
    uint32_t a;
    asm("{ .reg .u64 t; cvta.to.shared.u64 t, %1; cvt.u32.u64 %0, t; }" : "=r"(a) : "l"(p));
    return a;
}
__device__ __forceinline__ void split2(float v0, float v1, uint32_t& hi, uint32_t& lo) {
    __nv_bfloat16 h0 = __float2bfloat16(v0);
    __nv_bfloat16 h1 = __float2bfloat16(v1);
    float r0 = v0 - __bfloat162float(h0);
    float r1 = v1 - __bfloat162float(h1);
    __nv_bfloat16 l0 = __float2bfloat16(r0);
    __nv_bfloat16 l1 = __float2bfloat16(r1);
    hi = (uint32_t)__bfloat16_as_ushort(h0) | ((uint32_t)__bfloat16_as_ushort(h1) << 16);
    lo = (uint32_t)__bfloat16_as_ushort(l0) | ((uint32_t)__bfloat16_as_ushort(l1) << 16);
}
__device__ __forceinline__ void ldsm4(uint32_t& r0, uint32_t& r1, uint32_t& r2, uint32_t& r3,
                                      uint32_t addr) {
    asm volatile("ldmatrix.sync.aligned.m8n8.x4.shared.b16 {%0,%1,%2,%3}, [%4];"
                 : "=r"(r0), "=r"(r1), "=r"(r2), "=r"(r3) : "r"(addr));
}
__device__ __forceinline__ void mma_bf16(float* c, const uint32_t* a, uint32_t b0, uint32_t b1) {
    asm volatile(
        "mma.sync.aligned.m16n8k16.row.col.f32.bf16.bf16.f32 "
        "{%0,%1,%2,%3}, {%4,%5,%6,%7}, {%8,%9}, {%0,%1,%2,%3};"
        : "+f"(c[0]), "+f"(c[1]), "+f"(c[2]), "+f"(c[3])
        : "r"(a[0]), "r"(a[1]), "r"(a[2]), "r"(a[3]), "r"(b0), "r"(b1));
}
__device__ __forceinline__ void cp16(uint32_t dst, const void* src) {
    asm volatile("cp.async.cg.shared.global [%0], [%1], 16;" :: "r"(dst), "l"(src));
}

// ---------------- CSR build ----------------
__global__ void k_hist(const int* __restrict__ ei) {
    int stride = gridDim.x * blockDim.x;
    for (int e = blockIdx.x * blockDim.x + threadIdx.x; e < N_EDGESC; e += stride)
        atomicAdd(&g_deg[ei[N_EDGESC + e]], 1);
}

__global__ void k_scan(const int* __restrict__ batch) {
    __shared__ int s[1024];
    const int t = threadIdx.x;
    const int CHUNK = 98;
    int base = t * CHUNK;
    int loc = 0;
    for (int i = 0; i < CHUNK; ++i) {
        int idx = base + i;
        if (idx < N_NODESC) loc += g_deg[idx];
    }
    s[t] = loc;
    __syncthreads();
    for (int off = 1; off < 1024; off <<= 1) {
        int v = (t >= off) ? s[t - off] : 0;
        __syncthreads();
        s[t] += v;
        __syncthreads();
    }
    int run = s[t] - loc;
    for (int i = 0; i < CHUNK; ++i) {
        int idx = base + i;
        if (idx < N_NODESC) {
            g_ptr[idx] = run;
            g_cur[idx] = run;
            run += g_deg[idx];
        }
    }
    if (t == 1023) g_ptr[N_NODESC] = s[1023];
    {
        int g = t;
        int lo = 0, hi = N_NODESC;
        while (lo < hi) {
            int mid = (lo + hi) >> 1;
            if (batch[mid] < g) lo = mid + 1; else hi = mid;
        }
        g_gstart[g] = lo;
        if (t == 1023) g_gstart[NUM_GRAPHSC] = N_NODESC;
    }
}

__global__ void k_scatter(const int* __restrict__ ei) {
    int stride = gridDim.x * blockDim.x;
    for (int e = blockIdx.x * blockDim.x + threadIdx.x; e < N_EDGESC; e += stride) {
        int d = ei[N_EDGESC + e];
        int p = atomicAdd(&g_cur[d], 1);
        g_col[p] = ei[e];
    }
}

// ---------------- weight prep: W[k][n] -> BT planes [n][k] bf16 hi/lo ----------------
__global__ void k_wprep(const float* __restrict__ w0, const float* __restrict__ w1,
                        const float* __restrict__ w2, const float* __restrict__ w3,
                        const float* __restrict__ w4) {
    int widx = blockIdx.x;
    const float* w = (widx == 0) ? w0 : (widx == 1) ? w1 : (widx == 2) ? w2
                     : (widx == 3) ? w3 : w4;
    for (int it = 0; it < 32; ++it) {
        int lin = threadIdx.x + it * 256;     // 0..8191
        int kp = lin & 63;
        int n = lin >> 6;
        float v0 = w[(2 * kp) * 128 + n];
        float v1 = w[(2 * kp + 1) * 128 + n];
        uint32_t hi, lo;
        split2(v0, v1, hi, lo);
        int idx = widx * PLANE_U32 + n * PLANE_W + kp;
        g_wbhi[idx] = hi;
        g_wblo[idx] = lo;
    }
    if (threadIdx.x < 128) {
        int n = threadIdx.x;
#pragma unroll
        for (int p = 64; p < 68; ++p) {
            g_wbhi[widx * PLANE_U32 + n * PLANE_W + p] = 0;
            g_wblo[widx * PLANE_U32 + n * PLANE_W + p] = 0;
        }
    }
}

// ---------------- layer 0 aggregation (7 feats) ----------------
__global__ void k_agg0(const float* __restrict__ x) {
    int gidx = blockIdx.x * blockDim.x + threadIdx.x;
    int node = gidx >> 5;
    int lane = gidx & 31;
    if (node >= N_NODESC) return;
    float acc[IN_FEATC];
#pragma unroll
    for (int f = 0; f < IN_FEATC; ++f) acc[f] = 0.f;
    int s = g_ptr[node], e = g_ptr[node + 1];
    for (int p = s + lane; p < e; p += 32) {
        int src = g_col[p];
        const float* xp = x + (size_t)src * IN_FEATC;
#pragma unroll
        for (int f = 0; f < IN_FEATC; ++f) acc[f] += xp[f];
    }
#pragma unroll
    for (int f = 0; f < IN_FEATC; ++f) {
#pragma unroll
        for (int off = 16; off > 0; off >>= 1)
            acc[f] += __shfl_down_sync(0xffffffffu, acc[f], off);
    }
    if (lane == 0) {
        const float* xp = x + (size_t)node * IN_FEATC;
        float* zp = g_z0 + (size_t)node * IN_FEATC;
#pragma unroll
        for (int f = 0; f < IN_FEATC; ++f) zp[f] = xp[f] + acc[f];
    }
}

// ---------------- main aggregation: z[n] = h[n] + sum h[src] (4x unrolled gather) ----------------
__global__ void k_agg(const float* __restrict__ h, int ldh) {
    int gidx = blockIdx.x * blockDim.x + threadIdx.x;
    int node = gidx >> 5;
    int lane = gidx & 31;
    if (node >= N_NODESC) return;
    int fo = lane << 2;
    const float* hp = h + fo;
    float4 acc = *(const float4*)(h + (size_t)node * ldh + fo);
    int s = g_ptr[node], e = g_ptr[node + 1];
    int p = s;
    for (; p + 4 <= e; p += 4) {
        int s0 = g_col[p], s1 = g_col[p + 1], s2 = g_col[p + 2], s3 = g_col[p + 3];
        float4 v0 = *(const float4*)(hp + (size_t)s0 * ldh);
        float4 v1 = *(const float4*)(hp + (size_t)s1 * ldh);
        float4 v2 = *(const float4*)(hp + (size_t)s2 * ldh);
        float4 v3 = *(const float4*)(hp + (size_t)s3 * ldh);
        acc.x += (v0.x + v1.x) + (v2.x + v3.x);
        acc.y += (v0.y + v1.y) + (v2.y + v3.y);
        acc.z += (v0.z + v1.z) + (v2.z + v3.z);
        acc.w += (v0.w + v1.w) + (v2.w + v3.w);
    }
    for (; p < e; ++p) {
        int src = g_col[p];
        float4 v = *(const float4*)(hp + (size_t)src * ldh);
        acc.x += v.x; acc.y += v.y; acc.z += v.z; acc.w += v.w;
    }
    *(float4*)(g_z + (size_t)node * HC + fo) = acc;
}

// ---------------- tensor-core MLP via mma.sync bf16 3-term split ----------------
// smem byte layout: biases + A hi/lo + B1 hi/lo + B2 hi/lo (all planes resident)
#define ROW_B 272                 // bytes per plane row (68 u32)
#define PLANE_B (128 * ROW_B)     // 34816
#define SM_BS1 0
#define SM_BS2 512
#define SM_AHI 1024
#define SM_ALO (1024 + PLANE_B)
#define SM_B1H (1024 + 2 * PLANE_B)
#define SM_B1L (1024 + 3 * PLANE_B)
#define SM_B2H (1024 + 4 * PLANE_B)
#define SM_B2L (1024 + 5 * PLANE_B)
#define SM_TOTAL (1024 + 6 * PLANE_B)   // 209920 bytes

// per-warp mainloop: acc[2][8][4] over 32 rows (m0) x 64 cols (n0)
__device__ __forceinline__ void mma_main(uint32_t ahi, uint32_t alo, uint32_t bhi, uint32_t blo,
                                         int m0, int n0, int lane, float acc[2][8][4]) {
#pragma unroll
    for (int i = 0; i < 2; ++i)
#pragma unroll
        for (int j = 0; j < 8; ++j)
#pragma unroll
            for (int q = 0; q < 4; ++q) acc[i][j][q] = 0.f;

    const uint32_t a_off = (uint32_t)(m0 + (lane & 15)) * ROW_B + ((lane & 16) ? 16 : 0);
    const uint32_t b_off = (uint32_t)(n0 + (lane & 7) + ((lane & 16) ? 8 : 0)) * ROW_B
                           + ((lane & 8) ? 16 : 0);
#pragma unroll
    for (int ks = 0; ks < 8; ++ks) {
        const uint32_t kb = ks * 32;
        uint32_t Ah[2][4], Al[2][4];
#pragma unroll
        for (int mt = 0; mt < 2; ++mt) {
            uint32_t ad = a_off + (uint32_t)(mt * 16) * ROW_B + kb;
            ldsm4(Ah[mt][0], Ah[mt][1], Ah[mt][2], Ah[mt][3], ahi + ad);
            ldsm4(Al[mt][0], Al[mt][1], Al[mt][2], Al[mt][3], alo + ad);
        }
#pragma unroll
        for (int np = 0; np < 4; ++np) {
            uint32_t bd = b_off + (uint32_t)(np * 16) * ROW_B + kb;
            uint32_t Bh[4], Bl[4];
            ldsm4(Bh[0], Bh[1], Bh[2], Bh[3], bhi + bd);
            ldsm4(Bl[0], Bl[1], Bl[2], Bl[3], blo + bd);
#pragma unroll
            for (int sub = 0; sub < 2; ++sub) {
                int nt = np * 2 + sub;
#pragma unroll
                for (int mt = 0; mt < 2; ++mt) {
                    float* c = acc[mt][nt];
                    mma_bf16(c, Ah[mt], Bh[sub * 2], Bh[sub * 2 + 1]);
                    mma_bf16(c, Ah[mt], Bl[sub * 2], Bl[sub * 2 + 1]);
                    mma_bf16(c, Al[mt], Bh[sub * 2], Bh[sub * 2 + 1]);
                }
            }
        }
    }
}

// mode 0: A = relu(z0 @ wraw + bias1) computed in-kernel (K=7), then GEMM(B1)+bias2 -> OUT
// mode 1: A = split(Ain), GEMM(B1)+bias1 -> relu -> split -> GEMM(B2)+bias2 -> OUT
__global__ void __launch_bounds__(256, 1)
k_mlp(const float* __restrict__ Ain, int mode, const float* __restrict__ wraw,
      const float* __restrict__ bias1, int bidx1, int bidx2,
      const float* __restrict__ bias2,
      float* __restrict__ OUT, int ldout, int M) {
    extern __shared__ char sm[];
    const uint32_t smb = smem_u32(sm);
    float* bs1 = (float*)(sm + SM_BS1);
    float* bs2 = (float*)(sm + SM_BS2);
    const int tid = threadIdx.x;
    const int lane = tid & 31;
    const int warp = tid >> 5;
    const int g = lane >> 2, tg = lane & 3;
    const int row0 = blockIdx.x * 128;
    const int m0 = (warp & 3) * 32;
    const int n0 = (warp >> 2) * 64;

    // async-stage weight planes (B1; and B2 for mode 1)
    {
        const uint4* s1h = (const uint4*)(g_wbhi + bidx1 * PLANE_U32);
        const uint4* s1l = (const uint4*)(g_wblo + bidx1 * PLANE_U32);
        const uint4* s2h = (const uint4*)(g_wbhi + bidx2 * PLANE_U32);
        const uint4* s2l = (const uint4*)(g_wblo + bidx2 * PLANE_U32);
        for (int i = tid; i < PLANE_U32 / 4; i += 256) {
            cp16(smb + SM_B1H + i * 16, s1h + i);
            cp16(smb + SM_B1L + i * 16, s1l + i);
            if (mode) {
                cp16(smb + SM_B2H + i * 16, s2h + i);
                cp16(smb + SM_B2L + i * 16, s2l + i);
            }
        }
        asm volatile("cp.async.commit_group;" ::: "memory");
        if (tid < 128) {
            bs1[tid] = bias1[tid];
            bs2[tid] = bias2[tid];
        }
    }

    if (mode == 0) {
        // fused fc7: stage z0 tile + w1 raw into (unused) B2 region
        float* z0s = (float*)(sm + SM_B2H);            // 128*7 floats
        float* ws  = (float*)(sm + SM_B2L);            // 7*128 floats
        for (int i = tid; i < 128 * IN_FEATC; i += 256) {
            int r = i / IN_FEATC, k = i % IN_FEATC;
            int row = row0 + r;
            z0s[i] = (row < M) ? Ain[(size_t)row * IN_FEATC + k] : 0.f;
        }
        for (int i = tid; i < IN_FEATC * HC; i += 256) ws[i] = wraw[i];
        __syncthreads();
#pragma unroll 4
        for (int it = 0; it < 16; ++it) {
            int lin = tid + it * 256;
            int r = lin >> 5;
            int k4 = (lin & 31) << 2;
            float o[4];
#pragma unroll
            for (int j = 0; j < 4; ++j) {
                int c = k4 + j;
                float a = bs1[c];
#pragma unroll
                for (int kk = 0; kk < IN_FEATC; ++kk)
                    a = fmaf(z0s[r * IN_FEATC + kk], ws[kk * HC + c], a);
                o[j] = fmaxf(a, 0.f);
            }
            uint32_t h0, l0, h1, l1;
            split2(o[0], o[1], h0, l0);
            split2(o[2], o[3], h1, l1);
            uint32_t off = (uint32_t)r * ROW_B + (uint32_t)k4 * 2;
            *(uint2*)(sm + SM_AHI + off) = make_uint2(h0, h1);
            *(uint2*)(sm + SM_ALO + off) = make_uint2(l0, l1);
        }
    } else {
        // stage A: fp32 gmem (stride HC) -> split bf16 hi/lo planes
#pragma unroll 4
        for (int it = 0; it < 16; ++it) {
            int lin = tid + it * 256;
            int r = lin >> 5;
            int k4 = (lin & 31) << 2;
            float4 v = make_float4(0.f, 0.f, 0.f, 0.f);
            int row = row0 + r;
            if (row < M) v = *(const float4*)(Ain + (size_t)row * HC + k4);
            uint32_t h0, l0, h1, l1;
            split2(v.x, v.y, h0, l0);
            split2(v.z, v.w, h1, l1);
            uint32_t off = (uint32_t)r * ROW_B + (uint32_t)k4 * 2;
            *(uint2*)(sm + SM_AHI + off) = make_uint2(h0, h1);
            *(uint2*)(sm + SM_ALO + off) = make_uint2(l0, l1);
        }
    }
    asm volatile("cp.async.wait_group 0;" ::: "memory");
    __syncthreads();

    float acc[2][8][4];
    mma_main(smb + SM_AHI, smb + SM_ALO, smb + SM_B1H, smb + SM_B1L, m0, n0, lane, acc);

    if (mode == 0) {
        // epilogue: OUT = relu(acc + bias2)
#pragma unroll
        for (int mt = 0; mt < 2; ++mt) {
#pragma unroll
            for (int nt = 0; nt < 8; ++nt) {
                int c = n0 + nt * 8 + 2 * tg;
                float bx = bs2[c], by = bs2[c + 1];
                int ra = row0 + m0 + mt * 16 + g;
                int rb = ra + 8;
                if (ra < M) {
                    float2 v = make_float2(fmaxf(acc[mt][nt][0] + bx, 0.f),
                                           fmaxf(acc[mt][nt][1] + by, 0.f));
                    *(float2*)(OUT + (size_t)ra * ldout + c) = v;
                }
                if (rb < M) {
                    float2 v = make_float2(fmaxf(acc[mt][nt][2] + bx, 0.f),
                                           fmaxf(acc[mt][nt][3] + by, 0.f));
                    *(float2*)(OUT + (size_t)rb * ldout + c) = v;
                }
            }
        }
        return;
    }

    __syncthreads();  // all warps done reading A planes

    // t = relu(acc + bias1) -> split back into A planes
#pragma unroll
    for (int mt = 0; mt < 2; ++mt) {
#pragma unroll
        for (int nt = 0; nt < 8; ++nt) {
            int c = n0 + nt * 8 + 2 * tg;
            float bx = bs1[c], by = bs1[c + 1];
            int ra = m0 + mt * 16 + g;
            int rb = ra + 8;
            uint32_t hi, lo;
            split2(fmaxf(acc[mt][nt][0] + bx, 0.f), fmaxf(acc[mt][nt][1] + by, 0.f), hi, lo);
            uint32_t off = (uint32_t)ra * ROW_B + (uint32_t)c * 2;
            *(uint32_t*)(sm + SM_AHI + off) = hi;
            *(uint32_t*)(sm + SM_ALO + off) = lo;
            split2(fmaxf(acc[mt][nt][2] + bx, 0.f), fmaxf(acc[mt][nt][3] + by, 0.f), hi, lo);
            off = (uint32_t)rb * ROW_B + (uint32_t)c * 2;
            *(uint32_t*)(sm + SM_AHI + off) = hi;
            *(uint32_t*)(sm + SM_ALO + off) = lo;
        }
    }
    __syncthreads();

    mma_main(smb + SM_AHI, smb + SM_ALO, smb + SM_B2H, smb + SM_B2L, m0, n0, lane, acc);

    // final epilogue: OUT = relu(acc + bias2)
#pragma unroll
    for (int mt = 0; mt < 2; ++mt) {
#pragma unroll
        for (int nt = 0; nt < 8; ++nt) {
            int c = n0 + nt * 8 + 2 * tg;
            float bx = bs2[c], by = bs2[c + 1];
            int ra = row0 + m0 + mt * 16 + g;
            int rb = ra + 8;
            if (ra < M) {
                float2 v = make_float2(fmaxf(acc[mt][nt][0] + bx, 0.f),
                                       fmaxf(acc[mt][nt][1] + by, 0.f));
                *(float2*)(OUT + (size_t)ra * ldout + c) = v;
            }
            if (rb < M) {
                float2 v = make_float2(fmaxf(acc[mt][nt][2] + bx, 0.f),
                                       fmaxf(acc[mt][nt][3] + by, 0.f));
                *(float2*)(OUT + (size_t)rb * ldout + c) = v;
            }
        }
    }
}

// ---------------- global add pool ----------------
__global__ void k_pool() {
    int g = blockIdx.x;
    int f = threadIdx.x;
    int s = g_gstart[g], e = g_gstart[g + 1];
    float acc = 0.f;
    for (int n = s; n < e; ++n) acc += g_hcat[(size_t)n * H3C + f];
    g_pool[(size_t)g * H3C + f] = acc;
}

// ---------------- classifier stage 1 ----------------
__global__ void k_clf1(const float* __restrict__ w, const float* __restrict__ b,
                       const float* __restrict__ gamma, const float* __restrict__ beta,
                       const float* __restrict__ mean, const float* __restrict__ var) {
    __shared__ float gs[16 * H3C];
    const int r0 = blockIdx.x * 16;
    for (int i = threadIdx.x; i < 16 * H3C; i += blockDim.x)
        gs[i] = g_pool[(size_t)r0 * H3C + i];
    __syncthreads();
    const int c = threadIdx.x;
    float acc[16];
#pragma unroll
    for (int i = 0; i < 16; ++i) acc[i] = 0.f;
    for (int k = 0; k < H3C; ++k) {
        float wv = w[k * 256 + c];
#pragma unroll
        for (int i = 0; i < 16; ++i) acc[i] = fmaf(gs[i * H3C + k], wv, acc[i]);
    }
    float bb = b[c];
    float sc = rsqrtf(var[c] + BN_EPSF) * gamma[c];
    float mn = mean[c];
    float bt = beta[c];
#pragma unroll
    for (int i = 0; i < 16; ++i) {
        float v = (acc[i] + bb - mn) * sc + bt;
        g_z1[(size_t)(r0 + i) * 256 + c] = fmaxf(v, 0.f);
    }
}

// ---------------- classifier stage 2 ----------------
__global__ void k_clf2(const float* __restrict__ w2, const float* __restrict__ b2,
                       float* __restrict__ out) {
    __shared__ float w2s[512];
    __shared__ float b2s[2];
    for (int i = threadIdx.x; i < 512; i += blockDim.x) w2s[i] = w2[i];
    if (threadIdx.x < 2) b2s[threadIdx.x] = b2[threadIdx.x];
    __syncthreads();
    int warp = threadIdx.x >> 5;
    int lane = threadIdx.x & 31;
    int r = blockIdx.x * 8 + warp;
    float a0 = 0.f, a1 = 0.f;
    for (int k = lane; k < 256; k += 32) {
        float v = g_z1[(size_t)r * 256 + k];
        a0 = fmaf(v, w2s[2 * k], a0);
        a1 = fmaf(v, w2s[2 * k + 1], a1);
    }
#pragma unroll
    for (int off = 16; off > 0; off >>= 1) {
        a0 += __shfl_down_sync(0xffffffffu, a0, off);
        a1 += __shfl_down_sync(0xffffffffu, a1, off);
    }
    if (lane == 0) {
        out[2 * r] = a0 + b2s[0];
        out[2 * r + 1] = a1 + b2s[1];
    }
}

// ---------------- launch ----------------
extern "C" void kernel_launch(void* const* d_in, const int* in_sizes, int n_in,
                              void* d_out, int out_size) {
    const float* x      = (const float*)d_in[0];
    const int*   ei     = (const int*)d_in[1];
    const int*   batch  = (const int*)d_in[2];
    const float* w1[3]  = {(const float*)d_in[3], (const float*)d_in[7],  (const float*)d_in[11]};
    const float* b1[3]  = {(const float*)d_in[4], (const float*)d_in[8],  (const float*)d_in[12]};
    const float* w2[3]  = {(const float*)d_in[5], (const float*)d_in[9],  (const float*)d_in[13]};
    const float* b2[3]  = {(const float*)d_in[6], (const float*)d_in[10], (const float*)d_in[14]};
    const float* clf_w1 = (const float*)d_in[15];
    const float* clf_b1 = (const float*)d_in[16];
    const float* clf_w2 = (const float*)d_in[17];
    const float* clf_b2 = (const float*)d_in[18];
    const float* bn_g   = (const float*)d_in[19];
    const float* bn_b   = (const float*)d_in[20];
    const float* bn_m   = (const float*)d_in[21];
    const float* bn_v   = (const float*)d_in[22];
    float* out = (float*)d_out;

    float *p_z0, *p_z, *p_hcat;
    int* p_deg;
    cudaGetSymbolAddress((void**)&p_z0, g_z0);
    cudaGetSymbolAddress((void**)&p_z, g_z);
    cudaGetSymbolAddress((void**)&p_hcat, g_hcat);
    cudaGetSymbolAddress((void**)&p_deg, g_deg);

    cudaFuncSetAttribute(k_mlp, cudaFuncAttributeMaxDynamicSharedMemorySize, SM_TOTAL);

    // weight prep (independent) + CSR build
    k_wprep<<<5, 256>>>(w2[0], w1[1], w2[1], w1[2], w2[2]);
    cudaMemsetAsync(p_deg, 0, N_NODESC * sizeof(int));
    k_hist<<<1024, 256>>>(ei);
    k_scan<<<1, 1024>>>(batch);
    k_scatter<<<1024, 256>>>(ei);

    const int aggBlocks = N_NODESC / 8;
    const int gemmBlocks = (N_NODESC + 127) / 128;

    // layer 0: agg(7) -> fused fc7 + tensor GEMM
    k_agg0<<<aggBlocks, 256>>>(x);
    k_mlp<<<gemmBlocks, 256, SM_TOTAL>>>(p_z0, 0, w1[0], b1[0], 0, 0, b2[0],
                                         p_hcat + 0, H3C, N_NODESC);

    // layers 1,2: agg -> fused two-stage tensor MLP
    for (int l = 1; l < 3; ++l) {
        k_agg<<<aggBlocks, 256>>>(p_hcat + (l - 1) * HC, H3C);
        int wa = (l == 1) ? 1 : 3;
        int wb = (l == 1) ? 2 : 4;
        k_mlp<<<gemmBlocks, 256, SM_TOTAL>>>(p_z, 1, w1[l], b1[l], wa, wb, b2[l],
                                             p_hcat + l * HC, H3C, N_NODESC);
    }

    // pool + classifier
    k_pool<<<NUM_GRAPHSC, H3C>>>();
    k_clf1<<<NUM_GRAPHSC / 16, 256>>>(clf_w1, clf_b1, bn_g, bn_b, bn_m, bn_v);
    k_clf2<<<NUM_GRAPHSC / 8, 256>>>(clf_w2, clf_b2, out);
}